// round 1
// baseline (speedup 1.0000x reference)
#include <cuda_runtime.h>
#include <cuda_bf16.h>
#include <math_constants.h>

// Problem constants
#define BATCH 4
#define SEQ   2048
#define EMB   1024
#define HEADS 16
#define HDIM  64
#define MTOT  (BATCH * SEQ)          // 8192
#define QKVN  (3 * EMB)              // 3072

// ---------------------------------------------------------------------------
// Scratch (device globals; no dynamic allocation allowed)
// ---------------------------------------------------------------------------
__device__ float g_q[BATCH * HEADS * SEQ * HDIM];    // [B,H,N,D]
__device__ float g_k[BATCH * HEADS * SEQ * HDIM];
__device__ float g_v[BATCH * HEADS * SEQ * HDIM];
__device__ float g_attn[MTOT * EMB];                 // [B*N, E] attention output

// ---------------------------------------------------------------------------
// Kernel 1: QKV GEMM  C[m,n] = x[m,:] . qkv_w[n,:] + qkv_b[n]
//           scattered into g_q/g_k/g_v with layout [B,H,N,D]
// 128x128 tile, BK=8, 256 threads, 8x8 microtile.
// ---------------------------------------------------------------------------
__global__ __launch_bounds__(256)
void qkv_gemm_kernel(const float* __restrict__ x,
                     const float* __restrict__ w,
                     const float* __restrict__ bias) {
    __shared__ float As[8][132];
    __shared__ float Bs[8][132];

    const int m0 = blockIdx.y * 128;
    const int n0 = blockIdx.x * 128;
    const int t  = threadIdx.x;
    const int tx = t & 15;
    const int ty = t >> 4;
    const int lrow  = t >> 1;
    const int lhalf = t & 1;

    const float* aptr = x + (size_t)(m0 + lrow) * EMB + lhalf * 4;
    const float* bptr = w + (size_t)(n0 + lrow) * EMB + lhalf * 4;

    float acc[8][8];
#pragma unroll
    for (int i = 0; i < 8; i++)
#pragma unroll
        for (int j = 0; j < 8; j++) acc[i][j] = 0.f;

    for (int k0 = 0; k0 < EMB; k0 += 8) {
        float4 av = *(const float4*)(aptr + k0);
        float4 bv = *(const float4*)(bptr + k0);
        __syncthreads();
        As[lhalf * 4 + 0][lrow] = av.x;
        As[lhalf * 4 + 1][lrow] = av.y;
        As[lhalf * 4 + 2][lrow] = av.z;
        As[lhalf * 4 + 3][lrow] = av.w;
        Bs[lhalf * 4 + 0][lrow] = bv.x;
        Bs[lhalf * 4 + 1][lrow] = bv.y;
        Bs[lhalf * 4 + 2][lrow] = bv.z;
        Bs[lhalf * 4 + 3][lrow] = bv.w;
        __syncthreads();
#pragma unroll
        for (int kk = 0; kk < 8; kk++) {
            float4 a0 = *(const float4*)&As[kk][ty * 8];
            float4 a1 = *(const float4*)&As[kk][ty * 8 + 4];
            float4 b0 = *(const float4*)&Bs[kk][tx * 8];
            float4 b1 = *(const float4*)&Bs[kk][tx * 8 + 4];
            float a[8] = {a0.x, a0.y, a0.z, a0.w, a1.x, a1.y, a1.z, a1.w};
            float b[8] = {b0.x, b0.y, b0.z, b0.w, b1.x, b1.y, b1.z, b1.w};
#pragma unroll
            for (int i = 0; i < 8; i++)
#pragma unroll
                for (int j = 0; j < 8; j++) acc[i][j] += a[i] * b[j];
        }
    }

    // Epilogue: add bias, scatter into Q/K/V [B,H,N,D]
#pragma unroll
    for (int i = 0; i < 8; i++) {
        const int m  = m0 + ty * 8 + i;
        const int bb = m >> 11;          // m / SEQ
        const int nn = m & (SEQ - 1);
#pragma unroll
        for (int j = 0; j < 8; j++) {
            const int n = n0 + tx * 8 + j;
            float val = acc[i][j] + bias[n];
            const int s = n >> 10;       // which of q/k/v
            const int r = n & 1023;
            const int h = r >> 6;
            const int d = r & 63;
            const size_t idx = (((size_t)(bb * HEADS + h)) * SEQ + nn) * HDIM + d;
            if (s == 0)      g_q[idx] = val;
            else if (s == 1) g_k[idx] = val;
            else             g_v[idx] = val;
        }
    }
}

// ---------------------------------------------------------------------------
// Kernel 2: flash attention (fp32, online softmax).
// Grid: (SEQ/128, B*H). Block 256 threads.
// Q tile 128 rows, KV tile 64 rows. Microtiles: S is 128x64 -> 8x4/thread.
// ---------------------------------------------------------------------------
#define FLASH_SMEM_FLOATS (64 * 132 + 64 * 68 + 64 * 68 + 128 * 68)

__global__ __launch_bounds__(256)
void flash_attn_kernel() {
    extern __shared__ float sm[];
    float* Qs = sm;                   // [64 d][132] (k-major, 128 rows padded)
    float* Ks = Qs + 64 * 132;        // [64 d][68]  (k-major, 64 cols padded)
    float* Vs = Ks + 64 * 68;         // [64 c][68]  (natural, 64 dims padded)
    float* Ps = Vs + 64 * 68;         // [128 r][68]

    const int t  = threadIdx.x;
    const int tx = t & 15;
    const int ty = t >> 4;
    const int bh = blockIdx.y;
    const int q0 = blockIdx.x * 128;

    const float* Qg = g_q + ((size_t)bh * SEQ + q0) * HDIM;
    const float* Kg = g_k + (size_t)bh * SEQ * HDIM;
    const float* Vg = g_v + (size_t)bh * SEQ * HDIM;

    // Load Q tile transposed: Qs[d][row]
    for (int idx = t; idx < 128 * 16; idx += 256) {
        const int row = idx >> 4, q4 = idx & 15;
        float4 v = *(const float4*)(Qg + row * HDIM + q4 * 4);
        Qs[(q4 * 4 + 0) * 132 + row] = v.x;
        Qs[(q4 * 4 + 1) * 132 + row] = v.y;
        Qs[(q4 * 4 + 2) * 132 + row] = v.z;
        Qs[(q4 * 4 + 3) * 132 + row] = v.w;
    }

    float m_i[8], l_i[8], o[8][4];
#pragma unroll
    for (int i = 0; i < 8; i++) {
        m_i[i] = -CUDART_INF_F;
        l_i[i] = 0.f;
#pragma unroll
        for (int j = 0; j < 4; j++) o[i][j] = 0.f;
    }

    for (int kv0 = 0; kv0 < SEQ; kv0 += 64) {
        __syncthreads();  // previous PV done before tile overwrite
        for (int idx = t; idx < 64 * 16; idx += 256) {
            const int row = idx >> 4, q4 = idx & 15;
            float4 kv = *(const float4*)(Kg + (kv0 + row) * HDIM + q4 * 4);
            Ks[(q4 * 4 + 0) * 68 + row] = kv.x;
            Ks[(q4 * 4 + 1) * 68 + row] = kv.y;
            Ks[(q4 * 4 + 2) * 68 + row] = kv.z;
            Ks[(q4 * 4 + 3) * 68 + row] = kv.w;
            float4 vv = *(const float4*)(Vg + (kv0 + row) * HDIM + q4 * 4);
            *(float4*)&Vs[row * 68 + q4 * 4] = vv;
        }
        __syncthreads();

        // S = Q @ K^T  (128x64, per thread 8x4)
        float s[8][4];
#pragma unroll
        for (int i = 0; i < 8; i++)
#pragma unroll
            for (int j = 0; j < 4; j++) s[i][j] = 0.f;

        for (int k = 0; k < 64; k++) {
            float4 a0 = *(const float4*)&Qs[k * 132 + ty * 8];
            float4 a1 = *(const float4*)&Qs[k * 132 + ty * 8 + 4];
            float4 bv = *(const float4*)&Ks[k * 68 + tx * 4];
            float a[8] = {a0.x, a0.y, a0.z, a0.w, a1.x, a1.y, a1.z, a1.w};
            float b[4] = {bv.x, bv.y, bv.z, bv.w};
#pragma unroll
            for (int i = 0; i < 8; i++)
#pragma unroll
                for (int j = 0; j < 4; j++) s[i][j] += a[i] * b[j];
        }

        // Online softmax update (scale 1/sqrt(64) = 0.125)
#pragma unroll
        for (int i = 0; i < 8; i++) {
#pragma unroll
            for (int j = 0; j < 4; j++) s[i][j] *= 0.125f;
            float rm = fmaxf(fmaxf(s[i][0], s[i][1]), fmaxf(s[i][2], s[i][3]));
            rm = fmaxf(rm, __shfl_xor_sync(0xffffffffu, rm, 1, 16));
            rm = fmaxf(rm, __shfl_xor_sync(0xffffffffu, rm, 2, 16));
            rm = fmaxf(rm, __shfl_xor_sync(0xffffffffu, rm, 4, 16));
            rm = fmaxf(rm, __shfl_xor_sync(0xffffffffu, rm, 8, 16));
            const float nm = fmaxf(m_i[i], rm);
            const float corr = __expf(m_i[i] - nm);
            m_i[i] = nm;
            float4 p;
            p.x = __expf(s[i][0] - nm);
            p.y = __expf(s[i][1] - nm);
            p.z = __expf(s[i][2] - nm);
            p.w = __expf(s[i][3] - nm);
            float rs = p.x + p.y + p.z + p.w;
            rs += __shfl_xor_sync(0xffffffffu, rs, 1, 16);
            rs += __shfl_xor_sync(0xffffffffu, rs, 2, 16);
            rs += __shfl_xor_sync(0xffffffffu, rs, 4, 16);
            rs += __shfl_xor_sync(0xffffffffu, rs, 8, 16);
            l_i[i] = l_i[i] * corr + rs;
#pragma unroll
            for (int j = 0; j < 4; j++) o[i][j] *= corr;
            *(float4*)&Ps[(ty * 8 + i) * 68 + tx * 4] = p;
        }
        __syncthreads();

        // O += P @ V  (128x64x64, per thread 8x4)
        for (int c = 0; c < 64; c++) {
            float4 vv = *(const float4*)&Vs[c * 68 + tx * 4];
#pragma unroll
            for (int i = 0; i < 8; i++) {
                const float p = Ps[(ty * 8 + i) * 68 + c];
                o[i][0] += p * vv.x;
                o[i][1] += p * vv.y;
                o[i][2] += p * vv.z;
                o[i][3] += p * vv.w;
            }
        }
    }

    // Epilogue: write to g_attn in [B*N, E] layout (col = h*64 + d)
    const int b = bh >> 4;
    const int h = bh & 15;
#pragma unroll
    for (int i = 0; i < 8; i++) {
        const float inv = 1.f / l_i[i];
        float4 r;
        r.x = o[i][0] * inv;
        r.y = o[i][1] * inv;
        r.z = o[i][2] * inv;
        r.w = o[i][3] * inv;
        const size_t row = (size_t)b * SEQ + q0 + ty * 8 + i;
        *(float4*)&g_attn[row * EMB + h * HDIM + tx * 4] = r;
    }
}

// ---------------------------------------------------------------------------
// Kernel 3: output projection  out[m,n] = g_attn[m,:] . out_w[n,:] + out_b[n]
// ---------------------------------------------------------------------------
__global__ __launch_bounds__(256)
void out_gemm_kernel(const float* __restrict__ w,
                     const float* __restrict__ bias,
                     float* __restrict__ out) {
    __shared__ float As[8][132];
    __shared__ float Bs[8][132];

    const int m0 = blockIdx.y * 128;
    const int n0 = blockIdx.x * 128;
    const int t  = threadIdx.x;
    const int tx = t & 15;
    const int ty = t >> 4;
    const int lrow  = t >> 1;
    const int lhalf = t & 1;

    const float* aptr = g_attn + (size_t)(m0 + lrow) * EMB + lhalf * 4;
    const float* bptr = w + (size_t)(n0 + lrow) * EMB + lhalf * 4;

    float acc[8][8];
#pragma unroll
    for (int i = 0; i < 8; i++)
#pragma unroll
        for (int j = 0; j < 8; j++) acc[i][j] = 0.f;

    for (int k0 = 0; k0 < EMB; k0 += 8) {
        float4 av = *(const float4*)(aptr + k0);
        float4 bv = *(const float4*)(bptr + k0);
        __syncthreads();
        As[lhalf * 4 + 0][lrow] = av.x;
        As[lhalf * 4 + 1][lrow] = av.y;
        As[lhalf * 4 + 2][lrow] = av.z;
        As[lhalf * 4 + 3][lrow] = av.w;
        Bs[lhalf * 4 + 0][lrow] = bv.x;
        Bs[lhalf * 4 + 1][lrow] = bv.y;
        Bs[lhalf * 4 + 2][lrow] = bv.z;
        Bs[lhalf * 4 + 3][lrow] = bv.w;
        __syncthreads();
#pragma unroll
        for (int kk = 0; kk < 8; kk++) {
            float4 a0 = *(const float4*)&As[kk][ty * 8];
            float4 a1 = *(const float4*)&As[kk][ty * 8 + 4];
            float4 b0 = *(const float4*)&Bs[kk][tx * 8];
            float4 b1 = *(const float4*)&Bs[kk][tx * 8 + 4];
            float a[8] = {a0.x, a0.y, a0.z, a0.w, a1.x, a1.y, a1.z, a1.w};
            float b[8] = {b0.x, b0.y, b0.z, b0.w, b1.x, b1.y, b1.z, b1.w};
#pragma unroll
            for (int i = 0; i < 8; i++)
#pragma unroll
                for (int j = 0; j < 8; j++) acc[i][j] += a[i] * b[j];
        }
    }

#pragma unroll
    for (int i = 0; i < 8; i++) {
        const int m = m0 + ty * 8 + i;
        float4 r0, r1;
        r0.x = acc[i][0] + bias[n0 + tx * 8 + 0];
        r0.y = acc[i][1] + bias[n0 + tx * 8 + 1];
        r0.z = acc[i][2] + bias[n0 + tx * 8 + 2];
        r0.w = acc[i][3] + bias[n0 + tx * 8 + 3];
        r1.x = acc[i][4] + bias[n0 + tx * 8 + 4];
        r1.y = acc[i][5] + bias[n0 + tx * 8 + 5];
        r1.z = acc[i][6] + bias[n0 + tx * 8 + 6];
        r1.w = acc[i][7] + bias[n0 + tx * 8 + 7];
        *(float4*)&out[(size_t)m * EMB + n0 + tx * 8]     = r0;
        *(float4*)&out[(size_t)m * EMB + n0 + tx * 8 + 4] = r1;
    }
}

// ---------------------------------------------------------------------------
// Launcher
// ---------------------------------------------------------------------------
extern "C" void kernel_launch(void* const* d_in, const int* in_sizes, int n_in,
                              void* d_out, int out_size) {
    const float* x     = (const float*)d_in[0];
    const float* qkv_w = (const float*)d_in[1];
    const float* qkv_b = (const float*)d_in[2];
    const float* out_w = (const float*)d_in[3];
    const float* out_b = (const float*)d_in[4];
    float* out = (float*)d_out;

    const size_t flash_smem = FLASH_SMEM_FLOATS * sizeof(float);  // ~103.4 KB
    cudaFuncSetAttribute(flash_attn_kernel,
                         cudaFuncAttributeMaxDynamicSharedMemorySize,
                         (int)flash_smem);

    qkv_gemm_kernel<<<dim3(QKVN / 128, MTOT / 128), 256>>>(x, qkv_w, qkv_b);
    flash_attn_kernel<<<dim3(SEQ / 128, BATCH * HEADS), 256, flash_smem>>>();
    out_gemm_kernel<<<dim3(EMB / 128, MTOT / 128), 256>>>(out_w, out_b, out);
}

// round 2
// speedup vs baseline: 1.0018x; 1.0018x over previous
#include <cuda_runtime.h>
#include <cuda_bf16.h>
#include <math_constants.h>

// Problem constants
#define BATCH 4
#define SEQ   2048
#define EMB   1024
#define HEADS 16
#define HDIM  64
#define MTOT  (BATCH * SEQ)          // 8192
#define QKVN  (3 * EMB)              // 3072

// ---------------------------------------------------------------------------
// Scratch (device globals; no dynamic allocation allowed)
// ---------------------------------------------------------------------------
__device__ float g_q[BATCH * HEADS * SEQ * HDIM];    // [B,H,N,D]
__device__ float g_k[BATCH * HEADS * SEQ * HDIM];
__device__ float g_v[BATCH * HEADS * SEQ * HDIM];
__device__ float g_attn[MTOT * EMB];                 // [B*N, E] attention output

// ---------------------------------------------------------------------------
// Kernel 1: QKV GEMM  C[m,n] = x[m,:] . qkv_w[n,:] + qkv_b[n]
//           scattered into g_q/g_k/g_v with layout [B,H,N,D]
// 128x128 tile, BK=8, 256 threads, 8x8 microtile.
// ---------------------------------------------------------------------------
__global__ __launch_bounds__(256)
void qkv_gemm_kernel(const float* __restrict__ x,
                     const float* __restrict__ w,
                     const float* __restrict__ bias) {
    __shared__ float As[8][132];
    __shared__ float Bs[8][132];

    const int m0 = blockIdx.y * 128;
    const int n0 = blockIdx.x * 128;
    const int t  = threadIdx.x;
    const int tx = t & 15;
    const int ty = t >> 4;
    const int lrow  = t >> 1;
    const int lhalf = t & 1;

    const float* aptr = x + (size_t)(m0 + lrow) * EMB + lhalf * 4;
    const float* bptr = w + (size_t)(n0 + lrow) * EMB + lhalf * 4;

    float acc[8][8];
#pragma unroll
    for (int i = 0; i < 8; i++)
#pragma unroll
        for (int j = 0; j < 8; j++) acc[i][j] = 0.f;

    for (int k0 = 0; k0 < EMB; k0 += 8) {
        float4 av = *(const float4*)(aptr + k0);
        float4 bv = *(const float4*)(bptr + k0);
        __syncthreads();
        As[lhalf * 4 + 0][lrow] = av.x;
        As[lhalf * 4 + 1][lrow] = av.y;
        As[lhalf * 4 + 2][lrow] = av.z;
        As[lhalf * 4 + 3][lrow] = av.w;
        Bs[lhalf * 4 + 0][lrow] = bv.x;
        Bs[lhalf * 4 + 1][lrow] = bv.y;
        Bs[lhalf * 4 + 2][lrow] = bv.z;
        Bs[lhalf * 4 + 3][lrow] = bv.w;
        __syncthreads();
#pragma unroll
        for (int kk = 0; kk < 8; kk++) {
            float4 a0 = *(const float4*)&As[kk][ty * 8];
            float4 a1 = *(const float4*)&As[kk][ty * 8 + 4];
            float4 b0 = *(const float4*)&Bs[kk][tx * 8];
            float4 b1 = *(const float4*)&Bs[kk][tx * 8 + 4];
            float a[8] = {a0.x, a0.y, a0.z, a0.w, a1.x, a1.y, a1.z, a1.w};
            float b[8] = {b0.x, b0.y, b0.z, b0.w, b1.x, b1.y, b1.z, b1.w};
#pragma unroll
            for (int i = 0; i < 8; i++)
#pragma unroll
                for (int j = 0; j < 8; j++) acc[i][j] += a[i] * b[j];
        }
    }

    // Epilogue: add bias, scatter into Q/K/V [B,H,N,D]
#pragma unroll
    for (int i = 0; i < 8; i++) {
        const int m  = m0 + ty * 8 + i;
        const int bb = m >> 11;          // m / SEQ
        const int nn = m & (SEQ - 1);
#pragma unroll
        for (int j = 0; j < 8; j++) {
            const int n = n0 + tx * 8 + j;
            float val = acc[i][j] + bias[n];
            const int s = n >> 10;       // which of q/k/v
            const int r = n & 1023;
            const int h = r >> 6;
            const int d = r & 63;
            const size_t idx = (((size_t)(bb * HEADS + h)) * SEQ + nn) * HDIM + d;
            if (s == 0)      g_q[idx] = val;
            else if (s == 1) g_k[idx] = val;
            else             g_v[idx] = val;
        }
    }
}

// ---------------------------------------------------------------------------
// Kernel 2: flash attention (fp32, online softmax).
// Grid: (SEQ/128, B*H). Block 256 threads.
// Q tile 128 rows, KV tile 64 rows. Microtiles: S is 128x64 -> 8x4/thread.
// ---------------------------------------------------------------------------
#define FLASH_SMEM_FLOATS (64 * 132 + 64 * 68 + 64 * 68 + 128 * 68)

__global__ __launch_bounds__(256)
void flash_attn_kernel() {
    extern __shared__ float sm[];
    float* Qs = sm;                   // [64 d][132] (k-major, 128 rows padded)
    float* Ks = Qs + 64 * 132;        // [64 d][68]  (k-major, 64 cols padded)
    float* Vs = Ks + 64 * 68;         // [64 c][68]  (natural, 64 dims padded)
    float* Ps = Vs + 64 * 68;         // [128 r][68]

    const int t  = threadIdx.x;
    const int tx = t & 15;
    const int ty = t >> 4;
    const int bh = blockIdx.y;
    const int q0 = blockIdx.x * 128;

    const float* Qg = g_q + ((size_t)bh * SEQ + q0) * HDIM;
    const float* Kg = g_k + (size_t)bh * SEQ * HDIM;
    const float* Vg = g_v + (size_t)bh * SEQ * HDIM;

    // Load Q tile transposed: Qs[d][row]
    for (int idx = t; idx < 128 * 16; idx += 256) {
        const int row = idx >> 4, q4 = idx & 15;
        float4 v = *(const float4*)(Qg + row * HDIM + q4 * 4);
        Qs[(q4 * 4 + 0) * 132 + row] = v.x;
        Qs[(q4 * 4 + 1) * 132 + row] = v.y;
        Qs[(q4 * 4 + 2) * 132 + row] = v.z;
        Qs[(q4 * 4 + 3) * 132 + row] = v.w;
    }

    float m_i[8], l_i[8], o[8][4];
#pragma unroll
    for (int i = 0; i < 8; i++) {
        m_i[i] = -CUDART_INF_F;
        l_i[i] = 0.f;
#pragma unroll
        for (int j = 0; j < 4; j++) o[i][j] = 0.f;
    }

    for (int kv0 = 0; kv0 < SEQ; kv0 += 64) {
        __syncthreads();  // previous PV done before tile overwrite
        for (int idx = t; idx < 64 * 16; idx += 256) {
            const int row = idx >> 4, q4 = idx & 15;
            float4 kv = *(const float4*)(Kg + (kv0 + row) * HDIM + q4 * 4);
            Ks[(q4 * 4 + 0) * 68 + row] = kv.x;
            Ks[(q4 * 4 + 1) * 68 + row] = kv.y;
            Ks[(q4 * 4 + 2) * 68 + row] = kv.z;
            Ks[(q4 * 4 + 3) * 68 + row] = kv.w;
            float4 vv = *(const float4*)(Vg + (kv0 + row) * HDIM + q4 * 4);
            *(float4*)&Vs[row * 68 + q4 * 4] = vv;
        }
        __syncthreads();

        // S = Q @ K^T  (128x64, per thread 8x4)
        float s[8][4];
#pragma unroll
        for (int i = 0; i < 8; i++)
#pragma unroll
            for (int j = 0; j < 4; j++) s[i][j] = 0.f;

        for (int k = 0; k < 64; k++) {
            float4 a0 = *(const float4*)&Qs[k * 132 + ty * 8];
            float4 a1 = *(const float4*)&Qs[k * 132 + ty * 8 + 4];
            float4 bv = *(const float4*)&Ks[k * 68 + tx * 4];
            float a[8] = {a0.x, a0.y, a0.z, a0.w, a1.x, a1.y, a1.z, a1.w};
            float b[4] = {bv.x, bv.y, bv.z, bv.w};
#pragma unroll
            for (int i = 0; i < 8; i++)
#pragma unroll
                for (int j = 0; j < 4; j++) s[i][j] += a[i] * b[j];
        }

        // Online softmax update (scale 1/sqrt(64) = 0.125)
#pragma unroll
        for (int i = 0; i < 8; i++) {
#pragma unroll
            for (int j = 0; j < 4; j++) s[i][j] *= 0.125f;
            float rm = fmaxf(fmaxf(s[i][0], s[i][1]), fmaxf(s[i][2], s[i][3]));
            rm = fmaxf(rm, __shfl_xor_sync(0xffffffffu, rm, 1, 16));
            rm = fmaxf(rm, __shfl_xor_sync(0xffffffffu, rm, 2, 16));
            rm = fmaxf(rm, __shfl_xor_sync(0xffffffffu, rm, 4, 16));
            rm = fmaxf(rm, __shfl_xor_sync(0xffffffffu, rm, 8, 16));
            const float nm = fmaxf(m_i[i], rm);
            const float corr = __expf(m_i[i] - nm);
            m_i[i] = nm;
            float4 p;
            p.x = __expf(s[i][0] - nm);
            p.y = __expf(s[i][1] - nm);
            p.z = __expf(s[i][2] - nm);
            p.w = __expf(s[i][3] - nm);
            float rs = p.x + p.y + p.z + p.w;
            rs += __shfl_xor_sync(0xffffffffu, rs, 1, 16);
            rs += __shfl_xor_sync(0xffffffffu, rs, 2, 16);
            rs += __shfl_xor_sync(0xffffffffu, rs, 4, 16);
            rs += __shfl_xor_sync(0xffffffffu, rs, 8, 16);
            l_i[i] = l_i[i] * corr + rs;
#pragma unroll
            for (int j = 0; j < 4; j++) o[i][j] *= corr;
            *(float4*)&Ps[(ty * 8 + i) * 68 + tx * 4] = p;
        }
        __syncthreads();

        // O += P @ V  (128x64x64, per thread 8x4)
        for (int c = 0; c < 64; c++) {
            float4 vv = *(const float4*)&Vs[c * 68 + tx * 4];
#pragma unroll
            for (int i = 0; i < 8; i++) {
                const float p = Ps[(ty * 8 + i) * 68 + c];
                o[i][0] += p * vv.x;
                o[i][1] += p * vv.y;
                o[i][2] += p * vv.z;
                o[i][3] += p * vv.w;
            }
        }
    }

    // Epilogue: write to g_attn in [B*N, E] layout (col = h*64 + d)
    const int b = bh >> 4;
    const int h = bh & 15;
#pragma unroll
    for (int i = 0; i < 8; i++) {
        const float inv = 1.f / l_i[i];
        float4 r;
        r.x = o[i][0] * inv;
        r.y = o[i][1] * inv;
        r.z = o[i][2] * inv;
        r.w = o[i][3] * inv;
        const size_t row = (size_t)b * SEQ + q0 + ty * 8 + i;
        *(float4*)&g_attn[row * EMB + h * HDIM + tx * 4] = r;
    }
}

// ---------------------------------------------------------------------------
// Kernel 3: output projection  out[m,n] = g_attn[m,:] . out_w[n,:] + out_b[n]
// ---------------------------------------------------------------------------
__global__ __launch_bounds__(256)
void out_gemm_kernel(const float* __restrict__ w,
                     const float* __restrict__ bias,
                     float* __restrict__ out) {
    __shared__ float As[8][132];
    __shared__ float Bs[8][132];

    const int m0 = blockIdx.y * 128;
    const int n0 = blockIdx.x * 128;
    const int t  = threadIdx.x;
    const int tx = t & 15;
    const int ty = t >> 4;
    const int lrow  = t >> 1;
    const int lhalf = t & 1;

    const float* aptr = g_attn + (size_t)(m0 + lrow) * EMB + lhalf * 4;
    const float* bptr = w + (size_t)(n0 + lrow) * EMB + lhalf * 4;

    float acc[8][8];
#pragma unroll
    for (int i = 0; i < 8; i++)
#pragma unroll
        for (int j = 0; j < 8; j++) acc[i][j] = 0.f;

    for (int k0 = 0; k0 < EMB; k0 += 8) {
        float4 av = *(const float4*)(aptr + k0);
        float4 bv = *(const float4*)(bptr + k0);
        __syncthreads();
        As[lhalf * 4 + 0][lrow] = av.x;
        As[lhalf * 4 + 1][lrow] = av.y;
        As[lhalf * 4 + 2][lrow] = av.z;
        As[lhalf * 4 + 3][lrow] = av.w;
        Bs[lhalf * 4 + 0][lrow] = bv.x;
        Bs[lhalf * 4 + 1][lrow] = bv.y;
        Bs[lhalf * 4 + 2][lrow] = bv.z;
        Bs[lhalf * 4 + 3][lrow] = bv.w;
        __syncthreads();
#pragma unroll
        for (int kk = 0; kk < 8; kk++) {
            float4 a0 = *(const float4*)&As[kk][ty * 8];
            float4 a1 = *(const float4*)&As[kk][ty * 8 + 4];
            float4 b0 = *(const float4*)&Bs[kk][tx * 8];
            float4 b1 = *(const float4*)&Bs[kk][tx * 8 + 4];
            float a[8] = {a0.x, a0.y, a0.z, a0.w, a1.x, a1.y, a1.z, a1.w};
            float b[8] = {b0.x, b0.y, b0.z, b0.w, b1.x, b1.y, b1.z, b1.w};
#pragma unroll
            for (int i = 0; i < 8; i++)
#pragma unroll
                for (int j = 0; j < 8; j++) acc[i][j] += a[i] * b[j];
        }
    }

#pragma unroll
    for (int i = 0; i < 8; i++) {
        const int m = m0 + ty * 8 + i;
        float4 r0, r1;
        r0.x = acc[i][0] + bias[n0 + tx * 8 + 0];
        r0.y = acc[i][1] + bias[n0 + tx * 8 + 1];
        r0.z = acc[i][2] + bias[n0 + tx * 8 + 2];
        r0.w = acc[i][3] + bias[n0 + tx * 8 + 3];
        r1.x = acc[i][4] + bias[n0 + tx * 8 + 4];
        r1.y = acc[i][5] + bias[n0 + tx * 8 + 5];
        r1.z = acc[i][6] + bias[n0 + tx * 8 + 6];
        r1.w = acc[i][7] + bias[n0 + tx * 8 + 7];
        *(float4*)&out[(size_t)m * EMB + n0 + tx * 8]     = r0;
        *(float4*)&out[(size_t)m * EMB + n0 + tx * 8 + 4] = r1;
    }
}

// ---------------------------------------------------------------------------
// Launcher
// ---------------------------------------------------------------------------
extern "C" void kernel_launch(void* const* d_in, const int* in_sizes, int n_in,
                              void* d_out, int out_size) {
    const float* x     = (const float*)d_in[0];
    const float* qkv_w = (const float*)d_in[1];
    const float* qkv_b = (const float*)d_in[2];
    const float* out_w = (const float*)d_in[3];
    const float* out_b = (const float*)d_in[4];
    float* out = (float*)d_out;

    const size_t flash_smem = FLASH_SMEM_FLOATS * sizeof(float);  // ~103.4 KB
    cudaFuncSetAttribute(flash_attn_kernel,
                         cudaFuncAttributeMaxDynamicSharedMemorySize,
                         (int)flash_smem);

    qkv_gemm_kernel<<<dim3(QKVN / 128, MTOT / 128), 256>>>(x, qkv_w, qkv_b);
    flash_attn_kernel<<<dim3(SEQ / 128, BATCH * HEADS), 256, flash_smem>>>();
    out_gemm_kernel<<<dim3(EMB / 128, MTOT / 128), 256>>>(out_w, out_b, out);
}

// round 4
// speedup vs baseline: 6.7882x; 6.7759x over previous
#include <cuda_runtime.h>
#include <cuda_fp16.h>
#include <cstdint>

#define BATCH 4
#define SEQ   2048
#define EMB   1024
#define HEADS 16
#define MTOT  (BATCH * SEQ)
#define QKVN  (3 * EMB)

// ---------------------------------------------------------------------------
// PTX helpers (compute_100-safe: no tcgen05 / no *_100a features)
// ---------------------------------------------------------------------------
__device__ __forceinline__ uint32_t smem_u32(const void* p) {
    uint32_t a;
    asm("{ .reg .u64 t; cvta.to.shared.u64 t, %1; cvt.u32.u64 %0, t; }" : "=r"(a) : "l"(p));
    return a;
}
__device__ __forceinline__ float ex2(float x) {
    float y; asm("ex2.approx.f32 %0, %1;" : "=f"(y) : "f"(x)); return y;
}
__device__ __forceinline__ void hmma(float* c, const uint32_t* a, const uint32_t* b) {
    asm volatile("mma.sync.aligned.m16n8k16.row.col.f32.f16.f16.f32 "
                 "{%0,%1,%2,%3}, {%4,%5,%6,%7}, {%8,%9}, {%0,%1,%2,%3};"
                 : "+f"(c[0]), "+f"(c[1]), "+f"(c[2]), "+f"(c[3])
                 : "r"(a[0]), "r"(a[1]), "r"(a[2]), "r"(a[3]), "r"(b[0]), "r"(b[1]));
}
__device__ __forceinline__ void ldm4(uint32_t* r, uint32_t a) {
    asm volatile("ldmatrix.sync.aligned.m8n8.x4.shared.b16 {%0,%1,%2,%3}, [%4];"
                 : "=r"(r[0]), "=r"(r[1]), "=r"(r[2]), "=r"(r[3]) : "r"(a));
}
__device__ __forceinline__ void ldm4t(uint32_t* r, uint32_t a) {
    asm volatile("ldmatrix.sync.aligned.m8n8.x4.trans.shared.b16 {%0,%1,%2,%3}, [%4];"
                 : "=r"(r[0]), "=r"(r[1]), "=r"(r[2]), "=r"(r[3]) : "r"(a));
}
#define CP_ASYNC16(dst, src) \
    asm volatile("cp.async.cg.shared.global [%0], [%1], 16;" :: "r"(dst), "l"(src))
#define CP_COMMIT() asm volatile("cp.async.commit_group;" ::: "memory")
#define CP_WAIT(n)  asm volatile("cp.async.wait_group %0;" :: "n"(n) : "memory")

// ---------------------------------------------------------------------------
// Scratch
// ---------------------------------------------------------------------------
__device__ __half g_x16[(size_t)MTOT * EMB];
__device__ __half g_w16[(size_t)QKVN * EMB];
__device__ __half g_ow16[(size_t)EMB * EMB];
__device__ __half g_q[(size_t)64 * SEQ * 64];   // [BH][N][64], Q pre-scaled by 0.125*log2e
__device__ __half g_k[(size_t)64 * SEQ * 64];
__device__ __half g_v[(size_t)64 * SEQ * 64];
__device__ __half g_attn16[(size_t)MTOT * EMB];

// ---------------------------------------------------------------------------
// fp32 -> fp16 convert (8 elems/thread)
// ---------------------------------------------------------------------------
__global__ __launch_bounds__(256)
void conv16(const float* __restrict__ s, __half* __restrict__ d, int n8) {
    int i = blockIdx.x * 256 + threadIdx.x;
    if (i >= n8) return;
    float4 a = *(const float4*)(s + i * 8);
    float4 b = *(const float4*)(s + i * 8 + 4);
    __half2 h[4] = {__floats2half2_rn(a.x, a.y), __floats2half2_rn(a.z, a.w),
                    __floats2half2_rn(b.x, b.y), __floats2half2_rn(b.z, b.w)};
    *(uint2*)(d + i * 8)     = *(uint2*)&h[0];
    *(uint2*)(d + i * 8 + 4) = *(uint2*)&h[2];
}

// ---------------------------------------------------------------------------
// mma.sync GEMM: C[m,n] = A[m,:1024] . B[n,:1024] (+bias). Both K-major fp16.
// Block: 256 thr (8 warps, 4M x 2N), tile 128x128, K-chunk 64, cp.async 2-buf.
// MODE 0: A=g_x16, B=g_w16 -> scatter fp16 g_q/g_k/g_v (Q scaled)
// MODE 1: A=g_attn16, B=g_ow16 -> fp32 out
// smem per buffer: A 128x72, B 128x72 halves (ldmatrix conflict-free pad).
// ---------------------------------------------------------------------------
#define GPAD   72
#define GMATB  (128 * GPAD * 2)          // 18432 bytes per matrix
#define GBUF   (2 * GMATB)               // 36864 per buffer
#define GSMEM  (2 * GBUF)                // 73728 total

template <int MODE>
__global__ __launch_bounds__(256)
void gemm_hmma(const float* __restrict__ bias, float* __restrict__ out) {
    extern __shared__ char smc[];
    const uint32_t sb = smem_u32(smc);
    const int tid = threadIdx.x, wid = tid >> 5, lane = tid & 31;
    const int mw = wid & 3, nw = wid >> 2;           // warp tile: 32(M) x 64(N)
    const int gid = lane >> 2, tig = lane & 3;
    const int n0 = blockIdx.x * 128, m0 = blockIdx.y * 128;

    const __half* srcA = (MODE == 0 ? g_x16 : g_attn16) + (size_t)m0 * EMB;
    const __half* srcB = (MODE == 0 ? g_w16 : g_ow16) + (size_t)n0 * EMB;

    // per-thread load slots: 8 x uint4 (A:4, B:4)
    const int r_ = (tid >> 1) & 127;                  // row for this thread's pair
    // simpler indexing: idx = t*256 + tid, mat = idx>>10, row = (idx>>3)&127, seg = idx&7
    auto prefetch = [&](int buf, int c) {
#pragma unroll
        for (int t = 0; t < 8; t++) {
            int idx = t * 256 + tid;
            int mat = idx >> 10, r = (idx >> 3) & 127, seg = idx & 7;
            const __half* s = (mat ? srcB : srcA) + (size_t)r * EMB + c * 64 + seg * 8;
            uint32_t d = sb + buf * GBUF + mat * GMATB + (r * GPAD + seg * 8) * 2;
            CP_ASYNC16(d, s);
        }
    };
    (void)r_;

    float acc[2][8][4];
#pragma unroll
    for (int mi = 0; mi < 2; mi++)
#pragma unroll
        for (int nb = 0; nb < 8; nb++)
#pragma unroll
            for (int q = 0; q < 4; q++) acc[mi][nb][q] = 0.f;

    prefetch(0, 0);
    CP_COMMIT();

    const int arow = mw * 32 + (lane & 15);
    const int acol = (lane >> 4) * 8;
    const int nrow = nw * 64 + (lane & 7) + ((lane >> 4) << 3);
    const int kcol = ((lane >> 3) & 1) * 8;

    for (int c = 0; c < 16; c++) {
        const int buf = c & 1;
        if (c < 15) { prefetch(buf ^ 1, c + 1); CP_COMMIT(); CP_WAIT(1); }
        else        { CP_WAIT(0); }
        __syncthreads();

        const uint32_t ab = sb + buf * GBUF;
        const uint32_t bb = ab + GMATB;
#pragma unroll
        for (int ks = 0; ks < 4; ks++) {
            uint32_t af[2][4];
            ldm4(af[0], ab + ((arow)      * GPAD + ks * 16 + acol) * 2);
            ldm4(af[1], ab + ((arow + 16) * GPAD + ks * 16 + acol) * 2);
#pragma unroll
            for (int nt = 0; nt < 4; nt++) {
                uint32_t bf[4];
                ldm4(bf, bb + ((nt * 16 + nrow) * GPAD + ks * 16 + kcol) * 2);
#pragma unroll
                for (int mi = 0; mi < 2; mi++) {
                    hmma(acc[mi][nt * 2],     af[mi], bf);
                    hmma(acc[mi][nt * 2 + 1], af[mi], bf + 2);
                }
            }
        }
        __syncthreads();
    }

    // Epilogue
#pragma unroll
    for (int mi = 0; mi < 2; mi++) {
        const int mrow0 = m0 + mw * 32 + mi * 16 + gid;   // and +8
#pragma unroll
        for (int nb = 0; nb < 8; nb++) {
            const int n = n0 + nw * 64 + nb * 8 + 2 * tig;
            const float b0 = __ldg(bias + n), b1 = __ldg(bias + n + 1);
            float v00 = acc[mi][nb][0] + b0, v01 = acc[mi][nb][1] + b1;   // row mrow0
            float v10 = acc[mi][nb][2] + b0, v11 = acc[mi][nb][3] + b1;   // row mrow0+8
            if (MODE == 0) {
                const int s = n0 >> 10;
                const float sc = (s == 0) ? 0.18033688f : 1.0f;  // 0.125*log2(e)
                const int h = (n & 1023) >> 6, d0 = n & 63;
                __half* dst = (s == 0 ? g_q : s == 1 ? g_k : g_v);
                const int bb0 = mrow0 >> 11, nn0 = mrow0 & 2047;
                const int bb1 = (mrow0 + 8) >> 11, nn1 = (mrow0 + 8) & 2047;
                __half* p0 = dst + (((size_t)(bb0 * HEADS + h) * SEQ + nn0) << 6) + d0;
                __half* p1 = dst + (((size_t)(bb1 * HEADS + h) * SEQ + nn1) << 6) + d0;
                *(__half2*)p0 = __floats2half2_rn(v00 * sc, v01 * sc);
                *(__half2*)p1 = __floats2half2_rn(v10 * sc, v11 * sc);
            } else {
                float* p0 = out + (size_t)mrow0 * EMB + n;
                float* p1 = out + (size_t)(mrow0 + 8) * EMB + n;
                p0[0] = v00; p0[1] = v01;
                p1[0] = v10; p1[1] = v11;
            }
        }
    }
}

// ---------------------------------------------------------------------------
// Flash attention, mma.sync fp16, fp32 accum. Block=128 thr (4 warps).
// Q tile 64 rows (16/warp), KV tile 64. Q pre-scaled by 0.125*log2e -> exp2.
// ---------------------------------------------------------------------------
__global__ __launch_bounds__(128)
void flash16() {
    __shared__ __half Qs[64][72], Ks[64][72], Vs[64][72];
    const int tid = threadIdx.x, w = tid >> 5, lane = tid & 31;
    const int gid = lane >> 2, tig = lane & 3;
    const int bh = blockIdx.y, q0 = blockIdx.x * 64;
    const __half* Qg = g_q + ((size_t)bh * SEQ + q0) * 64;
    const __half* Kg = g_k + (size_t)bh * SEQ * 64;
    const __half* Vg = g_v + (size_t)bh * SEQ * 64;

#pragma unroll
    for (int t = 0; t < 4; t++) {
        int idx = t * 128 + tid, r = idx >> 3, seg = idx & 7;
        *(uint4*)&Qs[r][seg * 8] = *(const uint4*)(Qg + r * 64 + seg * 8);
    }
    __syncthreads();

    uint32_t aq[4][4];
    const uint32_t qb = smem_u32(&Qs[0][0]);
#pragma unroll
    for (int kb = 0; kb < 4; kb++)
        ldm4(aq[kb], qb + ((w * 16 + (lane & 15)) * 72 + kb * 16 + (lane >> 4) * 8) * 2);

    float m0 = -1e30f, m1 = -1e30f, l0 = 0.f, l1 = 0.f;
    float o[8][4];
#pragma unroll
    for (int j = 0; j < 8; j++)
#pragma unroll
        for (int q = 0; q < 4; q++) o[j][q] = 0.f;

    const uint32_t kb_ = smem_u32(&Ks[0][0]), vb_ = smem_u32(&Vs[0][0]);
    const int nrow = (lane & 7) + ((lane >> 4) << 3);
    const int kcol = ((lane >> 3) & 1) * 8;

    for (int kv0 = 0; kv0 < SEQ; kv0 += 64) {
        __syncthreads();
#pragma unroll
        for (int t = 0; t < 4; t++) {
            int idx = t * 128 + tid, r = idx >> 3, seg = idx & 7;
            *(uint4*)&Ks[r][seg * 8] = *(const uint4*)(Kg + (kv0 + r) * 64 + seg * 8);
            *(uint4*)&Vs[r][seg * 8] = *(const uint4*)(Vg + (kv0 + r) * 64 + seg * 8);
        }
        __syncthreads();

        float c[8][4];
#pragma unroll
        for (int j = 0; j < 8; j++)
#pragma unroll
            for (int q = 0; q < 4; q++) c[j][q] = 0.f;
#pragma unroll
        for (int nb2 = 0; nb2 < 4; nb2++)
#pragma unroll
            for (int kbk = 0; kbk < 4; kbk++) {
                uint32_t bf[4];
                ldm4(bf, kb_ + ((nb2 * 16 + nrow) * 72 + kbk * 16 + kcol) * 2);
                hmma(c[nb2 * 2],     aq[kbk], bf);
                hmma(c[nb2 * 2 + 1], aq[kbk], bf + 2);
            }

        float mx0 = -1e30f, mx1 = -1e30f;
#pragma unroll
        for (int j = 0; j < 8; j++) {
            mx0 = fmaxf(mx0, fmaxf(c[j][0], c[j][1]));
            mx1 = fmaxf(mx1, fmaxf(c[j][2], c[j][3]));
        }
        mx0 = fmaxf(mx0, __shfl_xor_sync(~0u, mx0, 1));
        mx0 = fmaxf(mx0, __shfl_xor_sync(~0u, mx0, 2));
        mx1 = fmaxf(mx1, __shfl_xor_sync(~0u, mx1, 1));
        mx1 = fmaxf(mx1, __shfl_xor_sync(~0u, mx1, 2));
        const float nm0 = fmaxf(m0, mx0), nm1 = fmaxf(m1, mx1);
        const float cr0 = ex2(m0 - nm0), cr1 = ex2(m1 - nm1);
        m0 = nm0; m1 = nm1;
        float rs0 = 0.f, rs1 = 0.f;
#pragma unroll
        for (int j = 0; j < 8; j++) {
            c[j][0] = ex2(c[j][0] - nm0); c[j][1] = ex2(c[j][1] - nm0);
            c[j][2] = ex2(c[j][2] - nm1); c[j][3] = ex2(c[j][3] - nm1);
            rs0 += c[j][0] + c[j][1];
            rs1 += c[j][2] + c[j][3];
        }
        rs0 += __shfl_xor_sync(~0u, rs0, 1); rs0 += __shfl_xor_sync(~0u, rs0, 2);
        rs1 += __shfl_xor_sync(~0u, rs1, 1); rs1 += __shfl_xor_sync(~0u, rs1, 2);
        l0 = l0 * cr0 + rs0; l1 = l1 * cr1 + rs1;
#pragma unroll
        for (int j = 0; j < 8; j++) {
            o[j][0] *= cr0; o[j][1] *= cr0; o[j][2] *= cr1; o[j][3] *= cr1;
        }

#pragma unroll
        for (int u = 0; u < 4; u++) {
            uint32_t pa[4];
            __half2 t0 = __floats2half2_rn(c[2 * u][0], c[2 * u][1]);
            __half2 t1 = __floats2half2_rn(c[2 * u][2], c[2 * u][3]);
            __half2 t2 = __floats2half2_rn(c[2 * u + 1][0], c[2 * u + 1][1]);
            __half2 t3 = __floats2half2_rn(c[2 * u + 1][2], c[2 * u + 1][3]);
            pa[0] = *(uint32_t*)&t0; pa[1] = *(uint32_t*)&t1;
            pa[2] = *(uint32_t*)&t2; pa[3] = *(uint32_t*)&t3;
#pragma unroll
            for (int db2 = 0; db2 < 4; db2++) {
                uint32_t vb[4];
                ldm4t(vb, vb_ + ((u * 16 + (lane & 15)) * 72 + db2 * 16 + (lane >> 4) * 8) * 2);
                hmma(o[db2 * 2],     pa, vb);
                hmma(o[db2 * 2 + 1], pa, vb + 2);
            }
        }
    }

    const int bb = bh >> 4, h = bh & 15;
    const float i0 = 1.f / l0, i1 = 1.f / l1;
    __half* dst = g_attn16 + ((size_t)bb * SEQ + q0 + w * 16) * EMB + h * 64;
#pragma unroll
    for (int j = 0; j < 8; j++) {
        const int col = j * 8 + 2 * tig;
        __half2 v0 = __floats2half2_rn(o[j][0] * i0, o[j][1] * i0);
        __half2 v1 = __floats2half2_rn(o[j][2] * i1, o[j][3] * i1);
        *(__half2*)(dst + (size_t)gid * EMB + col)       = v0;
        *(__half2*)(dst + (size_t)(gid + 8) * EMB + col) = v1;
    }
}

// ---------------------------------------------------------------------------
extern "C" void kernel_launch(void* const* d_in, const int* in_sizes, int n_in,
                              void* d_out, int out_size) {
    const float* x     = (const float*)d_in[0];
    const float* qkv_w = (const float*)d_in[1];
    const float* qkv_b = (const float*)d_in[2];
    const float* out_w = (const float*)d_in[3];
    const float* out_b = (const float*)d_in[4];
    float* out = (float*)d_out;

    __half* dx;  cudaGetSymbolAddress((void**)&dx, g_x16);
    __half* dw;  cudaGetSymbolAddress((void**)&dw, g_w16);
    __half* dow; cudaGetSymbolAddress((void**)&dow, g_ow16);

    cudaFuncSetAttribute(gemm_hmma<0>, cudaFuncAttributeMaxDynamicSharedMemorySize, GSMEM);
    cudaFuncSetAttribute(gemm_hmma<1>, cudaFuncAttributeMaxDynamicSharedMemorySize, GSMEM);

    conv16<<<(MTOT * EMB / 8 + 255) / 256, 256>>>(x, dx, MTOT * EMB / 8);
    conv16<<<(QKVN * EMB / 8 + 255) / 256, 256>>>(qkv_w, dw, QKVN * EMB / 8);
    conv16<<<(EMB * EMB / 8 + 255) / 256, 256>>>(out_w, dow, EMB * EMB / 8);

    gemm_hmma<0><<<dim3(QKVN / 128, MTOT / 128), 256, GSMEM>>>(qkv_b, nullptr);
    flash16<<<dim3(SEQ / 64, BATCH * HEADS), 128>>>();
    gemm_hmma<1><<<dim3(EMB / 128, MTOT / 128), 256, GSMEM>>>(out_b, out);
}